// round 1
// baseline (speedup 1.0000x reference)
#include <cuda_runtime.h>
#include <cstdint>

// Problem sizes (fixed)
#define M_DIM 8192
#define CO    128

// Tiling
constexpr int BM = 64;
constexpr int BN = 128;
constexpr int BK = 32;

constexpr int A_STRIDE = 36;              // padded floats per A smem row
constexpr int B_STRIDE = 136;             // padded floats per B smem row
constexpr int A_STAGE  = BM * A_STRIDE;   // 2304 floats
constexpr int B_STAGE  = BK * B_STRIDE;   // 4352 floats
constexpr int SMEM_FLOATS = 2 * (A_STAGE + B_STAGE);
constexpr int SMEM_BYTES  = SMEM_FLOATS * 4;   // 53248

// Scratch intermediates (no cudaMalloc allowed)
__device__ float g_T1[M_DIM * CO];
__device__ float g_S [M_DIM * CO];

__device__ __forceinline__ void cp_async16(uint32_t smem_addr, const void* gptr) {
    asm volatile("cp.async.cg.shared.global [%0], [%1], 16;\n"
                 :: "r"(smem_addr), "l"(gptr));
}

__device__ __forceinline__ uint32_t f2tf(float x) {
    uint32_t r;
    asm("cvt.rna.tf32.f32 %0, %1;\n" : "=r"(r) : "f"(x));
    return r;
}

__device__ __forceinline__ void mma_tf32(float* d, const uint32_t* a, const uint32_t* b) {
    asm volatile(
        "mma.sync.aligned.m16n8k8.row.col.f32.tf32.tf32.f32 "
        "{%0,%1,%2,%3}, {%4,%5,%6,%7}, {%8,%9}, {%0,%1,%2,%3};\n"
        : "+f"(d[0]), "+f"(d[1]), "+f"(d[2]), "+f"(d[3])
        : "r"(a[0]), "r"(a[1]), "r"(a[2]), "r"(a[3]),
          "r"(b[0]), "r"(b[1]));
}

// C[M,128] = A[M,K] @ B[K,128]; optional per-row scale on output.
// grid.x = M/BM, block = 256 threads (8 warps: 2 along M x 4 along N, 32x32 warp tiles)
__global__ void __launch_bounds__(256, 1)
gemm_tf32(const float* __restrict__ A, const float* __restrict__ B,
          float* __restrict__ C, int K, const float* __restrict__ scale)
{
    extern __shared__ float smem[];
    float* As = smem;                       // [2][BM][A_STRIDE]
    float* Bs = smem + 2 * A_STAGE;         // [2][BK][B_STRIDE]

    const uint32_t smem_base = (uint32_t)__cvta_generic_to_shared(smem);
    const uint32_t As_base = smem_base;
    const uint32_t Bs_base = smem_base + 2 * A_STAGE * 4;

    const int tid  = threadIdx.x;
    const int warp = tid >> 5;
    const int lane = tid & 31;
    const int warpM = warp & 1;        // 0..1
    const int warpN = warp >> 1;       // 0..3
    const int group = lane >> 2;       // 0..7
    const int tig   = lane & 3;        // 0..3

    const int blockRow = blockIdx.x * BM;

    float acc[2][4][4];
    #pragma unroll
    for (int mt = 0; mt < 2; mt++)
        #pragma unroll
        for (int nt = 0; nt < 4; nt++)
            #pragma unroll
            for (int i = 0; i < 4; i++) acc[mt][nt][i] = 0.0f;

    const int nK = K / BK;

    // tile loader: A tile BMxBK, B tile BKx128, via 16B cp.async
    auto load_tiles = [&](int kt, int buf) {
        const float* Ap = A + (size_t)blockRow * K + (size_t)kt * BK;
        #pragma unroll
        for (int i = 0; i < 2; i++) {
            int idx = tid + i * 256;       // 512 float4 in A tile
            int r  = idx >> 3;
            int c4 = idx & 7;
            uint32_t dst = As_base + (uint32_t)(buf * A_STAGE + r * A_STRIDE + c4 * 4) * 4;
            cp_async16(dst, Ap + (size_t)r * K + c4 * 4);
        }
        const float* Bp = B + (size_t)kt * BK * CO;
        #pragma unroll
        for (int i = 0; i < 4; i++) {
            int idx = tid + i * 256;       // 1024 float4 in B tile
            int r  = idx >> 5;
            int c4 = idx & 31;
            uint32_t dst = Bs_base + (uint32_t)(buf * B_STAGE + r * B_STRIDE + c4 * 4) * 4;
            cp_async16(dst, Bp + r * CO + c4 * 4);
        }
        asm volatile("cp.async.commit_group;\n");
    };

    load_tiles(0, 0);
    int buf = 0;

    for (int kt = 0; kt < nK; kt++) {
        asm volatile("cp.async.wait_group 0;\n");
        __syncthreads();

        if (kt + 1 < nK) load_tiles(kt + 1, buf ^ 1);

        const float* Ab = As + buf * A_STAGE;
        const float* Bb = Bs + buf * B_STAGE;

        #pragma unroll
        for (int ks = 0; ks < BK / 8; ks++) {
            uint32_t af[2][4];
            #pragma unroll
            for (int mt = 0; mt < 2; mt++) {
                int rbase = warpM * 32 + mt * 16;
                af[mt][0] = f2tf(Ab[(rbase + group    ) * A_STRIDE + ks * 8 + tig    ]);
                af[mt][1] = f2tf(Ab[(rbase + group + 8) * A_STRIDE + ks * 8 + tig    ]);
                af[mt][2] = f2tf(Ab[(rbase + group    ) * A_STRIDE + ks * 8 + tig + 4]);
                af[mt][3] = f2tf(Ab[(rbase + group + 8) * A_STRIDE + ks * 8 + tig + 4]);
            }
            uint32_t bf[4][2];
            #pragma unroll
            for (int nt = 0; nt < 4; nt++) {
                int col = warpN * 32 + nt * 8 + group;
                bf[nt][0] = f2tf(Bb[(ks * 8 + tig    ) * B_STRIDE + col]);
                bf[nt][1] = f2tf(Bb[(ks * 8 + tig + 4) * B_STRIDE + col]);
            }
            #pragma unroll
            for (int mt = 0; mt < 2; mt++)
                #pragma unroll
                for (int nt = 0; nt < 4; nt++)
                    mma_tf32(acc[mt][nt], af[mt], bf[nt]);
        }
        __syncthreads();
        buf ^= 1;
    }

    // Epilogue: optional per-row scale, 64-bit stores
    #pragma unroll
    for (int mt = 0; mt < 2; mt++) {
        int row0 = blockRow + warpM * 32 + mt * 16 + group;
        float s0 = scale ? scale[row0]     : 1.0f;
        float s1 = scale ? scale[row0 + 8] : 1.0f;
        #pragma unroll
        for (int nt = 0; nt < 4; nt++) {
            int col = warpN * 32 + nt * 8 + tig * 2;
            float2 v0 = make_float2(acc[mt][nt][0] * s0, acc[mt][nt][1] * s0);
            float2 v1 = make_float2(acc[mt][nt][2] * s1, acc[mt][nt][3] * s1);
            *reinterpret_cast<float2*>(&C[(size_t)row0 * CO + col])       = v0;
            *reinterpret_cast<float2*>(&C[(size_t)(row0 + 8) * CO + col]) = v1;
        }
    }
}

extern "C" void kernel_launch(void* const* d_in, const int* in_sizes, int n_in,
                              void* d_out, int out_size)
{
    const float* features     = (const float*)d_in[0];   // [8192,256]
    const float* wavelets     = (const float*)d_in[1];   // [8192,8192]
    const float* wavelets_inv = (const float*)d_in[2];   // [8192,8192]
    const float* weight       = (const float*)d_in[3];   // [256,128]
    const float* filt         = (const float*)d_in[4];   // [8192]
    float* out = (float*)d_out;                          // [8192,128]

    float *T1 = nullptr, *S = nullptr;
    cudaGetSymbolAddress((void**)&T1, g_T1);
    cudaGetSymbolAddress((void**)&S,  g_S);

    cudaFuncSetAttribute(gemm_tf32, cudaFuncAttributeMaxDynamicSharedMemorySize, SMEM_BYTES);

    dim3 grid(M_DIM / BM);   // 128 CTAs
    dim3 block(256);

    // T1 = features @ W
    gemm_tf32<<<grid, block, SMEM_BYTES>>>(features, weight, T1, 256, nullptr);
    // S = filt ⊙ (Winv @ T1)
    gemm_tf32<<<grid, block, SMEM_BYTES>>>(wavelets_inv, T1, S, M_DIM, filt);
    // out = Wav @ S
    gemm_tf32<<<grid, block, SMEM_BYTES>>>(wavelets, S, out, M_DIM, nullptr);
}

// round 3
// speedup vs baseline: 3.5207x; 3.5207x over previous
#include <cuda_runtime.h>
#include <cuda.h>
#include <cstdint>

// ---------------------------------------------------------------- arch gate
// tcgen05 is arch-accelerated: only legal in the compute_103a / compute_100a
// compilation passes. The plain compute_103 PTX pass must compile a fallback.
#if defined(__CUDA_ARCH_FEAT_SM103_ALL) || defined(__CUDA_ARCH_FEAT_SM100_ALL) || \
    defined(__CUDA_ARCH_FEAT_SM101_ALL) || defined(__CUDA_ARCH_FEAT_SM110_ALL)
#define HAS_TCGEN05 1
#else
#define HAS_TCGEN05 0
#endif

// ---------------------------------------------------------------- problem
#define M_DIM 8192
#define CO    128
#define KBIG  8192
#define SPLITK 2
#define KHALF (KBIG / SPLITK)

// ---------------------------------------------------------------- scratch
__device__ float g_T1t[CO * M_DIM];          // T1^T [128, 8192]
__device__ float g_St [CO * M_DIM];          // S^T  [128, 8192]
__device__ float g_P  [SPLITK * M_DIM * CO]; // split-K partials

// ---------------------------------------------------------------- helpers
__device__ __forceinline__ uint32_t smem_u32(const void* p) {
    uint32_t a;
    asm("{ .reg .u64 t; cvta.to.shared.u64 t, %1; cvt.u32.u64 %0, t; }" : "=r"(a) : "l"(p));
    return a;
}
__device__ __forceinline__ uint32_t elect_one() {
    uint32_t p;
    asm volatile("{ .reg .pred P; elect.sync _|P, 0xFFFFFFFF; selp.b32 %0, 1, 0, P; }" : "=r"(p));
    return p;
}
__device__ __forceinline__ uint32_t f2tf(float x) {
    uint32_t r; asm("cvt.rna.tf32.f32 %0, %1;" : "=r"(r) : "f"(x)); return r;
}
__device__ __forceinline__ void cp_async16(uint32_t s, const void* g) {
    asm volatile("cp.async.cg.shared.global [%0], [%1], 16;" :: "r"(s), "l"(g));
}
__device__ __forceinline__ void mma_legacy(float* d, const uint32_t* a, const uint32_t* b) {
    asm volatile("mma.sync.aligned.m16n8k8.row.col.f32.tf32.tf32.f32 "
                 "{%0,%1,%2,%3}, {%4,%5,%6,%7}, {%8,%9}, {%0,%1,%2,%3};"
                 : "+f"(d[0]), "+f"(d[1]), "+f"(d[2]), "+f"(d[3])
                 : "r"(a[0]), "r"(a[1]), "r"(a[2]), "r"(a[3]), "r"(b[0]), "r"(b[1]));
}

#define MBAR_INIT(a, c) asm volatile("mbarrier.init.shared.b64 [%0], %1;" :: "r"(a), "r"(c) : "memory")
#define MBAR_EXPECT_TX(a, b) asm volatile("mbarrier.arrive.expect_tx.shared.b64 _, [%0], %1;" :: "r"(a), "r"(b) : "memory")
#define MBAR_WAIT(a, ph) do { \
    uint32_t _m = (a), _p = (ph), _d; \
    asm volatile("{ .reg .pred P; mbarrier.try_wait.parity.acquire.cta.shared::cta.b64 P, [%1], %2; selp.b32 %0,1,0,P; }" \
                 : "=r"(_d) : "r"(_m), "r"(_p) : "memory"); \
    if (!_d) { \
        asm volatile("{ .reg .pred P1; WL%=: mbarrier.try_wait.parity.acquire.cta.shared::cta.b64 P1, [%0], %1, 0x989680; " \
                     "@P1 bra.uni WD%=; bra.uni WL%=; WD%=: }" :: "r"(_m), "r"(_p) : "memory"); \
    } } while (0)

__device__ __forceinline__ void tma_2d(uint32_t dst, const CUtensorMap* tm, int x, int y, uint32_t mbar) {
    asm volatile(
        "cp.async.bulk.tensor.2d.shared::cta.global.tile.mbarrier::complete_tx::bytes [%0], [%1, {%2, %3}], [%4];"
        :: "r"(dst), "l"(tm), "r"(x), "r"(y), "r"(mbar) : "memory");
}

__device__ __forceinline__ uint64_t make_desc_sw128(uint32_t addr) {
    return (2ULL << 61) | (1ULL << 46) | (64ULL << 32) | (1ULL << 16)
         | ((uint64_t)(addr >> 4) & 0x3FFF);
}

#if HAS_TCGEN05
__device__ __forceinline__ void mma_tf32_ss(uint32_t d, uint64_t ad, uint64_t bd,
                                            uint32_t idesc, uint32_t en) {
    asm volatile(
        "{ .reg .pred p; setp.ne.u32 p, %4, 0;"
        "  tcgen05.mma.cta_group::1.kind::tf32 [%0], %1, %2, %3, p; }"
        :: "r"(d), "l"(ad), "l"(bd), "r"(idesc), "r"(en) : "memory");
}

#define LDTM_X32(r, addr) \
    asm volatile("tcgen05.ld.sync.aligned.32x32b.x32.b32 " \
        "{%0,%1,%2,%3,%4,%5,%6,%7,%8,%9,%10,%11,%12,%13,%14,%15," \
        "%16,%17,%18,%19,%20,%21,%22,%23,%24,%25,%26,%27,%28,%29,%30,%31}, [%32];" \
        : "=r"((r)[0]),"=r"((r)[1]),"=r"((r)[2]),"=r"((r)[3]),"=r"((r)[4]),"=r"((r)[5]),"=r"((r)[6]),"=r"((r)[7]), \
          "=r"((r)[8]),"=r"((r)[9]),"=r"((r)[10]),"=r"((r)[11]),"=r"((r)[12]),"=r"((r)[13]),"=r"((r)[14]),"=r"((r)[15]), \
          "=r"((r)[16]),"=r"((r)[17]),"=r"((r)[18]),"=r"((r)[19]),"=r"((r)[20]),"=r"((r)[21]),"=r"((r)[22]),"=r"((r)[23]), \
          "=r"((r)[24]),"=r"((r)[25]),"=r"((r)[26]),"=r"((r)[27]),"=r"((r)[28]),"=r"((r)[29]),"=r"((r)[30]),"=r"((r)[31]) \
        : "r"(addr))
#endif

// ---------------------------------------------------------------- tcgen05 GEMM
// D[128,128] per CTA:  C[mRow0+r][c] = sum_k A[mRow0+r][k0+k] * Bt[c][k0+k]
// A: [M, K] row-major (K contiguous).  Bt: [128, K] row-major.
constexpr int NST = 6;
constexpr int BKT = 32;                       // k per stage (128 bytes)
constexpr int TILE_BYTES  = 128 * 128;        // 16 KB per operand tile
constexpr int STAGE_BYTES = 2 * TILE_BYTES;   // 32 KB
constexpr int GSMEM_BYTES = NST * STAGE_BYTES + 2048;   // 198656 B

// idesc: F32 accum, tf32 A/B, K-major both, N=128, M=128
constexpr uint32_t IDESC_TF32 =
    (1u << 4) | (2u << 7) | (2u << 10) | ((128u / 8) << 17) | ((128u / 16) << 24);

__global__ void __launch_bounds__(256, 1)
gemm_tc(const __grid_constant__ CUtensorMap tmA,
        const __grid_constant__ CUtensorMap tmB,
        const float* __restrict__ Araw, const float* __restrict__ Btraw,
        float* __restrict__ P, int kTiles)
{
    extern __shared__ char smem[];
    const int tid = threadIdx.x, wid = tid >> 5, lane = tid & 31;
    const int mRow0 = blockIdx.x * 128;
    const int k0 = blockIdx.y * KHALF;
    float* __restrict__ C = P + (size_t)blockIdx.y * M_DIM * CO;

#if HAS_TCGEN05
    const uint32_t sbase = smem_u32(smem);
    const uint32_t tile0 = (sbase + 256 + 1023) & ~1023u;

    auto fullb  = [&](int s) { return sbase + s * 16; };
    auto emptyb = [&](int s) { return sbase + s * 16 + 8; };
    const uint32_t doneb = sbase + NST * 16;
    const uint32_t tmemptr = sbase + 128 + NST * 16;

    if (wid == 5) {
        asm volatile("tcgen05.alloc.cta_group::1.sync.aligned.shared::cta.b32 [%0], %1;"
                     :: "r"(tmemptr), "r"(128u) : "memory");
    }
    if (tid == 0) {
        for (int s = 0; s < NST; s++) { MBAR_INIT(fullb(s), 1); MBAR_INIT(emptyb(s), 1); }
        MBAR_INIT(doneb, 1);
        asm volatile("fence.proxy.async.shared::cta;" ::: "memory");
    }
    __syncthreads();
    uint32_t tmem;
    asm volatile("ld.shared.b32 %0, [%1];" : "=r"(tmem) : "r"(tmemptr));

    if (wid == 4) {                       // ---- TMA producer
        if (elect_one()) {
            int s = 0, ph = 1;
            for (int kt = 0; kt < kTiles; kt++) {
                MBAR_WAIT(emptyb(s), ph);
                MBAR_EXPECT_TX(fullb(s), STAGE_BYTES);
                uint32_t dst = tile0 + s * STAGE_BYTES;
                tma_2d(dst,              &tmA, k0 + kt * BKT, mRow0, fullb(s));
                tma_2d(dst + TILE_BYTES, &tmB, k0 + kt * BKT, 0,     fullb(s));
                if (++s == NST) { s = 0; ph ^= 1; }
            }
        }
    } else if (wid == 5) {                // ---- MMA issuer
        if (elect_one()) {
            int s = 0, ph = 0;
            for (int kt = 0; kt < kTiles; kt++) {
                MBAR_WAIT(fullb(s), ph);
                uint64_t ad = make_desc_sw128(tile0 + s * STAGE_BYTES);
                uint64_t bd = make_desc_sw128(tile0 + s * STAGE_BYTES + TILE_BYTES);
                #pragma unroll
                for (int j = 0; j < 4; j++)
                    mma_tf32_ss(tmem, ad + 2 * j, bd + 2 * j, IDESC_TF32,
                                (kt > 0 || j > 0) ? 1u : 0u);
                asm volatile("tcgen05.commit.cta_group::1.mbarrier::arrive::one.shared::cluster.b64 [%0];"
                             :: "r"(emptyb(s)) : "memory");
                if (++s == NST) { s = 0; ph ^= 1; }
            }
            asm volatile("tcgen05.commit.cta_group::1.mbarrier::arrive::one.shared::cluster.b64 [%0];"
                         :: "r"(doneb) : "memory");
        }
    } else if (wid < 4) {                 // ---- epilogue (warps 0-3)
        MBAR_WAIT(doneb, 0);
        asm volatile("tcgen05.fence::after_thread_sync;" ::: "memory");
        const int row = mRow0 + wid * 32 + lane;
        float* Crow = C + (size_t)row * CO;
        #pragma unroll
        for (int ch = 0; ch < 4; ch++) {
            uint32_t r[32];
            LDTM_X32(r, tmem + ch * 32);
            asm volatile("tcgen05.wait::ld.sync.aligned;" ::: "memory");
            #pragma unroll
            for (int j = 0; j < 8; j++) {
                float4 v = make_float4(__uint_as_float(r[j*4+0]), __uint_as_float(r[j*4+1]),
                                       __uint_as_float(r[j*4+2]), __uint_as_float(r[j*4+3]));
                *reinterpret_cast<float4*>(Crow + ch * 32 + j * 4) = v;
            }
        }
        asm volatile("tcgen05.fence::before_thread_sync;" ::: "memory");
    }

    __syncthreads();
    if (wid == 5) {
        asm volatile("tcgen05.relinquish_alloc_permit.cta_group::1.sync.aligned;");
        asm volatile("tcgen05.dealloc.cta_group::1.sync.aligned.b32 %0, %1;" :: "r"(tmem), "r"(128u));
    }
#else
    // ---------------- fallback: legacy tf32 mma, cp.async double buffer ----------------
    // 8 warps: 4 along M (32 rows) x 2 along N (64 cols).
    constexpr int FSTRIDE = 36;
    constexpr int FSTAGE  = 128 * FSTRIDE;           // floats per operand tile
    float* As = reinterpret_cast<float*>(smem);                  // [2][128][36]
    float* Bs = reinterpret_cast<float*>(smem) + 2 * FSTAGE;     // [2][128][36]
    const uint32_t As_b = smem_u32(As), Bs_b = smem_u32(Bs);
    const int warpM = wid & 3, warpN = wid >> 2;
    const int group = lane >> 2, tig = lane & 3;

    float acc[2][8][4] = {};
    auto load_tiles = [&](int kt, int buf) {
        const float* Ap = Araw + (size_t)mRow0 * KBIG + k0 + (size_t)kt * BKT;
        const float* Bp = Btraw + (size_t)0 * KBIG + k0 + (size_t)kt * BKT;
        #pragma unroll
        for (int i = 0; i < 4; i++) {
            int idx = tid + i * 256, r = idx >> 3, c4 = idx & 7;    // 1024 float4
            cp_async16(As_b + (uint32_t)(buf * FSTAGE + r * FSTRIDE + c4 * 4) * 4,
                       Ap + (size_t)r * KBIG + c4 * 4);
            cp_async16(Bs_b + (uint32_t)(buf * FSTAGE + r * FSTRIDE + c4 * 4) * 4,
                       Bp + (size_t)r * KBIG + c4 * 4);
        }
        asm volatile("cp.async.commit_group;");
    };
    load_tiles(0, 0);
    int buf = 0;
    for (int kt = 0; kt < kTiles; kt++) {
        asm volatile("cp.async.wait_group 0;");
        __syncthreads();
        if (kt + 1 < kTiles) load_tiles(kt + 1, buf ^ 1);
        const float* Ab = As + buf * FSTAGE;
        const float* Bb = Bs + buf * FSTAGE;
        #pragma unroll
        for (int ks = 0; ks < BKT / 8; ks++) {
            uint32_t af[2][4], bf[8][2];
            #pragma unroll
            for (int mt = 0; mt < 2; mt++) {
                int rb = warpM * 32 + mt * 16;
                af[mt][0] = f2tf(Ab[(rb + group    ) * FSTRIDE + ks * 8 + tig    ]);
                af[mt][1] = f2tf(Ab[(rb + group + 8) * FSTRIDE + ks * 8 + tig    ]);
                af[mt][2] = f2tf(Ab[(rb + group    ) * FSTRIDE + ks * 8 + tig + 4]);
                af[mt][3] = f2tf(Ab[(rb + group + 8) * FSTRIDE + ks * 8 + tig + 4]);
            }
            #pragma unroll
            for (int nt = 0; nt < 8; nt++) {
                int col = warpN * 64 + nt * 8 + group;
                bf[nt][0] = f2tf(Bb[col * FSTRIDE + ks * 8 + tig    ]);
                bf[nt][1] = f2tf(Bb[col * FSTRIDE + ks * 8 + tig + 4]);
            }
            #pragma unroll
            for (int mt = 0; mt < 2; mt++)
                #pragma unroll
                for (int nt = 0; nt < 8; nt++)
                    mma_legacy(acc[mt][nt], af[mt], bf[nt]);
        }
        __syncthreads();
        buf ^= 1;
    }
    #pragma unroll
    for (int mt = 0; mt < 2; mt++) {
        int r0 = mRow0 + warpM * 32 + mt * 16 + group;
        #pragma unroll
        for (int nt = 0; nt < 8; nt++) {
            int col = warpN * 64 + nt * 8 + tig * 2;
            *reinterpret_cast<float2*>(&C[(size_t)r0 * CO + col]) =
                make_float2(acc[mt][nt][0], acc[mt][nt][1]);
            *reinterpret_cast<float2*>(&C[(size_t)(r0 + 8) * CO + col]) =
                make_float2(acc[mt][nt][2], acc[mt][nt][3]);
        }
    }
#endif
}

// ---------------------------------------------------------------- GEMM1 (legacy tf32 mma, K=256, writes T1^T with RNA)
constexpr int BM = 64, BK = 32;
constexpr int A_STRIDE = 36, B_STRIDE = 136;
constexpr int A_STAGE = BM * A_STRIDE, B_STAGE = BK * B_STRIDE;
constexpr int L_SMEM_BYTES = 2 * (A_STAGE + B_STAGE) * 4;

__global__ void __launch_bounds__(256, 1)
gemm1_t(const float* __restrict__ A, const float* __restrict__ B, float* __restrict__ Ct, int K)
{
    extern __shared__ float sm[];
    float* As = sm;  float* Bs = sm + 2 * A_STAGE;
    const uint32_t As_b = smem_u32(sm), Bs_b = As_b + 2 * A_STAGE * 4;
    const int tid = threadIdx.x, warp = tid >> 5, lane = tid & 31;
    const int warpM = warp & 1, warpN = warp >> 1, group = lane >> 2, tig = lane & 3;
    const int blockRow = blockIdx.x * BM;

    float acc[2][4][4] = {};
    const int nK = K / BK;
    auto load_tiles = [&](int kt, int buf) {
        const float* Ap = A + (size_t)blockRow * K + (size_t)kt * BK;
        #pragma unroll
        for (int i = 0; i < 2; i++) {
            int idx = tid + i * 256, r = idx >> 3, c4 = idx & 7;
            cp_async16(As_b + (uint32_t)(buf * A_STAGE + r * A_STRIDE + c4 * 4) * 4,
                       Ap + (size_t)r * K + c4 * 4);
        }
        const float* Bp = B + (size_t)kt * BK * CO;
        #pragma unroll
        for (int i = 0; i < 4; i++) {
            int idx = tid + i * 256, r = idx >> 5, c4 = idx & 31;
            cp_async16(Bs_b + (uint32_t)(buf * B_STAGE + r * B_STRIDE + c4 * 4) * 4,
                       Bp + r * CO + c4 * 4);
        }
        asm volatile("cp.async.commit_group;");
    };
    load_tiles(0, 0);
    int buf = 0;
    for (int kt = 0; kt < nK; kt++) {
        asm volatile("cp.async.wait_group 0;");
        __syncthreads();
        if (kt + 1 < nK) load_tiles(kt + 1, buf ^ 1);
        const float* Ab = As + buf * A_STAGE;
        const float* Bb = Bs + buf * B_STAGE;
        #pragma unroll
        for (int ks = 0; ks < BK / 8; ks++) {
            uint32_t af[2][4], bf[4][2];
            #pragma unroll
            for (int mt = 0; mt < 2; mt++) {
                int rb = warpM * 32 + mt * 16;
                af[mt][0] = f2tf(Ab[(rb + group    ) * A_STRIDE + ks * 8 + tig    ]);
                af[mt][1] = f2tf(Ab[(rb + group + 8) * A_STRIDE + ks * 8 + tig    ]);
                af[mt][2] = f2tf(Ab[(rb + group    ) * A_STRIDE + ks * 8 + tig + 4]);
                af[mt][3] = f2tf(Ab[(rb + group + 8) * A_STRIDE + ks * 8 + tig + 4]);
            }
            #pragma unroll
            for (int nt = 0; nt < 4; nt++) {
                int col = warpN * 32 + nt * 8 + group;
                bf[nt][0] = f2tf(Bb[(ks * 8 + tig    ) * B_STRIDE + col]);
                bf[nt][1] = f2tf(Bb[(ks * 8 + tig + 4) * B_STRIDE + col]);
            }
            #pragma unroll
            for (int mt = 0; mt < 2; mt++)
                #pragma unroll
                for (int nt = 0; nt < 4; nt++)
                    mma_legacy(acc[mt][nt], af[mt], bf[nt]);
        }
        __syncthreads();
        buf ^= 1;
    }
    // transposed + RNA-rounded epilogue: Ct[c][m]
    #pragma unroll
    for (int mt = 0; mt < 2; mt++) {
        int r0 = blockRow + warpM * 32 + mt * 16 + group;
        #pragma unroll
        for (int nt = 0; nt < 4; nt++) {
            int col = warpN * 32 + nt * 8 + tig * 2;
            Ct[(size_t)(col    ) * M_DIM + r0    ] = __uint_as_float(f2tf(acc[mt][nt][0]));
            Ct[(size_t)(col + 1) * M_DIM + r0    ] = __uint_as_float(f2tf(acc[mt][nt][1]));
            Ct[(size_t)(col    ) * M_DIM + r0 + 8] = __uint_as_float(f2tf(acc[mt][nt][2]));
            Ct[(size_t)(col + 1) * M_DIM + r0 + 8] = __uint_as_float(f2tf(acc[mt][nt][3]));
        }
    }
}

// ---------------------------------------------------------------- reduce kernels
// St[c][m] = rna(filt[m] * (P0[m][c] + P1[m][c]))   (32x32 smem transpose)
__global__ void reduce_scale_t(const float* __restrict__ P, const float* __restrict__ filt,
                               float* __restrict__ St)
{
    __shared__ float t[32][33];
    const int tx = threadIdx.x & 31, ty = threadIdx.x >> 5;   // 32 x 8
    const int m0 = blockIdx.x * 32, c0 = blockIdx.y * 32;
    #pragma unroll
    for (int i = 0; i < 4; i++) {
        int m = m0 + ty + i * 8;
        float v = (P[(size_t)m * CO + c0 + tx] + P[(size_t)(M_DIM + m) * CO + c0 + tx]) * filt[m];
        t[ty + i * 8][tx] = v;
    }
    __syncthreads();
    #pragma unroll
    for (int i = 0; i < 4; i++) {
        int c = c0 + ty + i * 8;
        St[(size_t)c * M_DIM + m0 + tx] = __uint_as_float(f2tf(t[tx][ty + i * 8]));
    }
}

__global__ void reduce_add(const float4* __restrict__ P, float4* __restrict__ out)
{
    int i = blockIdx.x * blockDim.x + threadIdx.x;   // 262144 float4
    float4 a = P[i], b = P[i + M_DIM * CO / 4];
    out[i] = make_float4(a.x + b.x, a.y + b.y, a.z + b.z, a.w + b.w);
}

// ---------------------------------------------------------------- tensormap setup
typedef CUresult (*EncodeTiledFn)(CUtensorMap*, CUtensorMapDataType, cuuint32_t, void*,
                                  const cuuint64_t*, const cuuint64_t*, const cuuint32_t*,
                                  const cuuint32_t*, CUtensorMapInterleave, CUtensorMapSwizzle,
                                  CUtensorMapL2promotion, CUtensorMapFloatOOBfill);

static void make_map(EncodeTiledFn enc, CUtensorMap* tm, const void* ptr,
                     uint64_t dimK, uint64_t dimM)
{
    cuuint64_t dims[2]    = { dimK, dimM };
    cuuint64_t strides[1] = { dimK * sizeof(float) };
    cuuint32_t box[2]     = { 32u, 128u };
    cuuint32_t es[2]      = { 1u, 1u };
    enc(tm, CU_TENSOR_MAP_DATA_TYPE_FLOAT32, 2, const_cast<void*>(ptr),
        dims, strides, box, es,
        CU_TENSOR_MAP_INTERLEAVE_NONE, CU_TENSOR_MAP_SWIZZLE_128B,
        CU_TENSOR_MAP_L2_PROMOTION_L2_128B, CU_TENSOR_MAP_FLOAT_OOB_FILL_NONE);
}

// ---------------------------------------------------------------- launch
extern "C" void kernel_launch(void* const* d_in, const int* in_sizes, int n_in,
                              void* d_out, int out_size)
{
    const float* features = (const float*)d_in[0];   // [8192,256]
    const float* wavelets = (const float*)d_in[1];   // [8192,8192]
    const float* winv     = (const float*)d_in[2];   // [8192,8192]
    const float* weight   = (const float*)d_in[3];   // [256,128]
    const float* filt     = (const float*)d_in[4];   // [8192]
    float* out = (float*)d_out;

    float *T1t = nullptr, *St = nullptr, *P = nullptr;
    cudaGetSymbolAddress((void**)&T1t, g_T1t);
    cudaGetSymbolAddress((void**)&St,  g_St);
    cudaGetSymbolAddress((void**)&P,   g_P);

    EncodeTiledFn enc = nullptr;
    cudaDriverEntryPointQueryResult qr;
    cudaGetDriverEntryPointByVersion("cuTensorMapEncodeTiled", (void**)&enc, 12000,
                                     cudaEnableDefault, &qr);

    alignas(64) CUtensorMap tmWinv, tmT1t, tmWav, tmSt;
    make_map(enc, &tmWinv, winv,     KBIG, M_DIM);
    make_map(enc, &tmT1t,  T1t,      KBIG, CO);
    make_map(enc, &tmWav,  wavelets, KBIG, M_DIM);
    make_map(enc, &tmSt,   St,       KBIG, CO);

    cudaFuncSetAttribute(gemm1_t, cudaFuncAttributeMaxDynamicSharedMemorySize, L_SMEM_BYTES);
    cudaFuncSetAttribute(gemm_tc, cudaFuncAttributeMaxDynamicSharedMemorySize, GSMEM_BYTES);

    // 1) T1^T = (features @ W)^T   (RNA-rounded)
    gemm1_t<<<M_DIM / BM, 256, L_SMEM_BYTES>>>(features, weight, T1t, 256);
    // 2) P = splitK partials of Winv @ T1
    gemm_tc<<<dim3(M_DIM / 128, SPLITK), 256, GSMEM_BYTES>>>(tmWinv, tmT1t, winv, T1t, P, KHALF / BKT);
    // 3) S^T = rna(filt * (P0+P1))^T
    reduce_scale_t<<<dim3(M_DIM / 32, CO / 32), 256>>>(P, filt, St);
    // 4) P = splitK partials of Wav @ S
    gemm_tc<<<dim3(M_DIM / 128, SPLITK), 256, GSMEM_BYTES>>>(tmWav, tmSt, wavelets, St, P, KHALF / BKT);
    // 5) out = P0 + P1
    reduce_add<<<M_DIM * CO / 4 / 256, 256>>>((const float4*)P, (float4*)out);
}